// round 6
// baseline (speedup 1.0000x reference)
#include <cuda_runtime.h>
#include <cstdint>

#define B_   4096
#define K_   1024
#define NG   4096    /* 4*H */
#define H_   1024
#define NM   4

#define STAGE_BYTES 16384     /* A 128x64 s8 (8KB) + B 128x64 s8 (8KB) */
#define NSTAGES     6
#define DSM_BYTES   (NSTAGES * STAGE_BYTES)   /* 96 KB */
#define CHUNKS_PER_BRANCH 16
#define TOTAL_CHUNKS      32

// ---- scratch (device globals; no runtime allocation) ----
__device__ signed char g_yA[2][NM][B_][K_];   // 32 MB  bit-plane ints (s8), K-major
__device__ signed char g_Wt[2][NG][K_];       //  8 MB  weight ints, transposed [N][K]
__device__ float       g_part[B_][NG];        // 64 MB  final gates

// ======================= small math helpers =======================
__device__ __forceinline__ float pact_f(float x, float a) {
    float ax = fabsf(x);
    float t  = fabsf(ax - a);
    float s  = (x > 0.f) ? 0.5f : ((x < 0.f) ? -0.5f : 0.f);
    return s * ((ax - t) + a);
}
__device__ __forceinline__ float qr8(float x, float r) {
    float xs = x / r;
    xs = fminf(fmaxf(xs, -0.9921875f), 0.9921875f);
    return (rintf(xs * 128.f) * 0.0078125f) * r;
}
__device__ __forceinline__ float sigmoidf_(float x) { return 1.f / (1.f + expf(-x)); }

// ======================= PTX helpers (sm_80-class only) =======================
__device__ __forceinline__ uint32_t s2u(const void* p) {
    uint32_t a;
    asm("{ .reg .u64 t; cvta.to.shared.u64 t, %1; cvt.u32.u64 %0, t; }" : "=r"(a) : "l"(p));
    return a;
}
__device__ __forceinline__ void cp16(uint32_t dst, const void* src) {
    asm volatile("cp.async.cg.shared.global [%0], [%1], 16;" :: "r"(dst), "l"(src) : "memory");
}
__device__ __forceinline__ void ldsm4(uint32_t addr, uint32_t& r0, uint32_t& r1,
                                      uint32_t& r2, uint32_t& r3) {
    asm volatile("ldmatrix.sync.aligned.m8n8.x4.shared.b16 {%0,%1,%2,%3}, [%4];"
                 : "=r"(r0), "=r"(r1), "=r"(r2), "=r"(r3) : "r"(addr));
}
__device__ __forceinline__ void imma(int* d, const uint32_t* a, const uint32_t* b) {
    asm volatile(
        "mma.sync.aligned.m16n8k32.row.col.s32.s8.s8.s32 "
        "{%0,%1,%2,%3}, {%4,%5,%6,%7}, {%8,%9}, {%0,%1,%2,%3};"
        : "+r"(d[0]), "+r"(d[1]), "+r"(d[2]), "+r"(d[3])
        : "r"(a[0]), "r"(a[1]), "r"(a[2]), "r"(a[3]), "r"(b[0]), "r"(b[1]));
}

// ======================= activation bit-split (s8 planes) =======================
__global__ void quant_acts_kernel(const float* __restrict__ input,
                                  const float* __restrict__ hx,
                                  const float* __restrict__ a1p,
                                  const float* __restrict__ a11p) {
    int idx = blockIdx.x * blockDim.x + threadIdx.x;
    if (idx >= 2 * (B_ * K_ / 4)) return;
    int branch = idx >> 20;               // B_*K_/4 = 2^20
    int r      = idx & ((B_ * K_ / 4) - 1);
    float a = branch ? *a11p : *a1p;
    float4 x4 = ((const float4*)(branch ? hx : input))[r];
    float xs[4] = {x4.x, x4.y, x4.z, x4.w};
    signed char o[NM][4];
#pragma unroll
    for (int j = 0; j < 4; j++) {
        float xv = pact_f(xs[j], a) / a;
        float beta = 1.f;
#pragma unroll
        for (int mq = 0; mq < NM; mq++) {
            float s = xv / beta;
            s = fminf(fmaxf(s, -0.9921875f), 0.9921875f);
            float yi = rintf(s * 128.f);       // exact int in [-127,127]
            xv = xv - (yi * 0.0078125f) * beta;
            o[mq][j] = (signed char)(int)yi;
            beta *= 0.5f;
        }
    }
#pragma unroll
    for (int mq = 0; mq < NM; mq++)
        ((char4*)&g_yA[branch][mq][0][0])[r] = make_char4(o[mq][0], o[mq][1], o[mq][2], o[mq][3]);
}

// ======================= weight quant + transpose (s8) =======================
__global__ void quant_w_kernel(const float* __restrict__ wih,
                               const float* __restrict__ whh) {
    __shared__ float tile[32][33];
    int branch = blockIdx.z;
    const float* w = branch ? whh : wih;
    int n0 = blockIdx.x * 32, k0 = blockIdx.y * 32;
    int tx = threadIdx.x, ty = threadIdx.y;   // 32 x 8
#pragma unroll
    for (int i = 0; i < 4; i++)
        tile[ty + i * 8][tx] = w[(size_t)(k0 + ty + i * 8) * NG + n0 + tx];
    __syncthreads();
#pragma unroll
    for (int i = 0; i < 4; i++) {
        float v = tile[tx][ty + i * 8];
        v = fminf(fmaxf(v, -0.9921875f), 0.9921875f);
        g_Wt[branch][n0 + ty + i * 8][k0 + tx] = (signed char)(int)rintf(v * 128.f);
    }
}

// ======================= int8 IMMA GEMM, both branches fused =======================
// CTA tile: M=128 (4 planes x 32 batch rows), N=128. BK=64.
// 8 warps: warp = (mh = warp&1: 16-batch-row half) x (nq = warp>>1: 32-col group).
// Each warp holds ALL 4 planes of its output block -> plane combine in-register.
// ONE CTA per SM (no 128-reg cap -> no spills); 6-stage cp.async pipeline.
// grid = (NG/128=32, B_/32=128).
__global__ void __launch_bounds__(256, 1) gemm_int8(const float* __restrict__ a1p,
                                                    const float* __restrict__ a11p,
                                                    const float* __restrict__ bih,
                                                    const float* __restrict__ bhh) {
    extern __shared__ __align__(128) char dsm[];
    __shared__ float comb[32 * 132];
    __shared__ float sbias[2][128];

    const int tid  = threadIdx.x;
    const int lane = tid & 31;
    const int warp = tid >> 5;
    const int mh   = warp & 1;     // 16-row half of the 32 batch rows
    const int nq   = warp >> 1;    // 32-col group (0..3)
    const int n0   = blockIdx.x * 128;
    const int blk  = blockIdx.y;

    if (tid < 128) {
        float v0 = fminf(fmaxf(bih[n0 + tid], -0.9921875f), 0.9921875f);
        sbias[0][tid] = rintf(v0 * 128.f);
        float v1 = fminf(fmaxf(bhh[n0 + tid], -0.9921875f), 0.9921875f);
        sbias[1][tid] = rintf(v1 * 128.f);
    }
    const float a1v  = *a1p;
    const float a11v = *a11p;

    const uint32_t smem = s2u(dsm);

    // ---- cp.async slots: 2 A-chunks + 2 B-chunks of 16B per thread per stage ----
    uint32_t a_src[2], a_dst[2], b_src[2], b_dst[2];
#pragma unroll
    for (int i = 0; i < 2; i++) {
        int id   = tid + 256 * i;
        int arow = id >> 2, ac = id & 3;        // 128 rows x 4 16B-chunks
        int plane = arow >> 5;
        int brow  = blk * 32 + (arow & 31);
        a_src[i] = (uint32_t)((plane * B_ + brow) * K_ + ac * 16);
        a_dst[i] = (uint32_t)(arow * 64 + (((ac ^ (arow >> 1)) & 3) << 4));
        int nrow = id >> 2, bc = id & 3;
        b_src[i] = (uint32_t)((n0 + nrow) * K_ + bc * 16);
        b_dst[i] = (uint32_t)(8192 + nrow * 64 + (((bc ^ (nrow >> 1)) & 3) << 4));
    }
    const char* gA = (const char*)&g_yA[0][0][0][0];
    const char* gB = (const char*)&g_Wt[0][0][0];

    // ---- ldmatrix lane constants ----
    const int m   = lane >> 3;          // which 8x8 matrix this lane addresses
    const int rr  = lane & 7;
    const int am2 = m >> 1;             // A: k-half bit
    const int amr = (m & 1) * 8;        // A: row-half
    uint32_t aoffx[4];
#pragma unroll
    for (int p = 0; p < 4; p++) {
        int rg = p * 32 + mh * 16 + amr + rr;
        aoffx[p] = (uint32_t)(rg * 64) | ((uint32_t)((rg >> 1) & 3) << 4);
    }
    const int bmr = m >> 1;             // B: j-within-pair bit
    const int bmc = m & 1;              // B: k-half bit
    uint32_t boffx[2];
#pragma unroll
    for (int t = 0; t < 2; t++) {
        int row = nq * 32 + t * 16 + bmr * 8 + rr;
        boffx[t] = (uint32_t)(8192 + row * 64) | ((uint32_t)((row >> 1) & 3) << 4);
    }

    int acc[4][4][4];                    // [plane][n-tile][frag]
#pragma unroll
    for (int p = 0; p < 4; p++)
#pragma unroll
        for (int j = 0; j < 4; j++)
#pragma unroll
            for (int d = 0; d < 4; d++) acc[p][j][d] = 0;

    auto load_stage = [&](int c, int stage) {
        int br = c >> 4;
        uint32_t k = (uint32_t)(c & 15) * 64;
        uint32_t st = smem + (uint32_t)stage * STAGE_BYTES;
        const char* A  = gA + (size_t)br * (NM * B_ * K_) + k;
        const char* Bp = gB + (size_t)br * (NG * K_) + k;
#pragma unroll
        for (int i = 0; i < 2; i++) {
            cp16(st + a_dst[i], A + a_src[i]);
            cp16(st + b_dst[i], Bp + b_src[i]);
        }
    };

    auto compute_stage = [&](int stage) {
        uint32_t st = smem + (uint32_t)stage * STAGE_BYTES;
#pragma unroll
        for (int s = 0; s < 2; s++) {          // two k32 steps per BK=64
            uint32_t aks = (uint32_t)(s * 2 + am2) << 4;
            uint32_t bks = (uint32_t)(s * 2 + bmc) << 4;
            uint32_t a[4][4];
#pragma unroll
            for (int p = 0; p < 4; p++)
                ldsm4((st + aoffx[p]) ^ aks, a[p][0], a[p][1], a[p][2], a[p][3]);
#pragma unroll
            for (int t = 0; t < 2; t++) {
                uint32_t b[4];
                ldsm4((st + boffx[t]) ^ bks, b[0], b[1], b[2], b[3]);
#pragma unroll
                for (int p = 0; p < 4; p++) {
                    imma(acc[p][2 * t],     a[p], &b[0]);
                    imma(acc[p][2 * t + 1], a[p], &b[2]);
                }
            }
        }
    };

    // plane combine fully in-register: each output element owned by ONE thread
    auto epilogue = [&](int br) {
        float av = br ? a11v : a1v;
        float sc0 = av * 0.0078125f;
#pragma unroll
        for (int j = 0; j < 4; j++) {
            int nnb = nq * 32 + j * 8 + (lane & 3) * 2;
#pragma unroll
            for (int d = 0; d < 4; d++) {
                int nn = nnb + (d & 1);
                int rw = mh * 16 + (lane >> 2) + (d >> 1) * 8;
                float bz = sbias[br][nn];
                float v = 0.f;
#pragma unroll
                for (int p = 0; p < 4; p++) {
                    float t = (float)acc[p][j][d] * 0.0078125f + bz;
                    float q = fminf(fmaxf(rintf(t), -127.f), 127.f);
                    v += q * (sc0 / (float)(1 << p));
                }
                float* dst = &comb[rw * 132 + nn];
                if (br == 0) *dst = v; else *dst += v;
            }
        }
    };

    // ---- pipeline: 6 stages, 32 chunks (branch = chunk>>4) ----
#pragma unroll
    for (int c = 0; c < NSTAGES - 1; c++) {
        load_stage(c, c);
        asm volatile("cp.async.commit_group;" ::: "memory");
    }
    int ls = NSTAGES - 1;   // next load stage slot
    int cs = 0;             // current compute stage slot
    for (int c = 0; c < TOTAL_CHUNKS; c++) {
        asm volatile("cp.async.wait_group %0;" :: "n"(NSTAGES - 2) : "memory");
        __syncthreads();
        if (c + NSTAGES - 1 < TOTAL_CHUNKS) load_stage(c + NSTAGES - 1, ls);
        asm volatile("cp.async.commit_group;" ::: "memory");
        if (++ls == NSTAGES) ls = 0;
        compute_stage(cs);
        if (++cs == NSTAGES) cs = 0;
        if (c == CHUNKS_PER_BRANCH - 1) {
            epilogue(0);
#pragma unroll
            for (int p = 0; p < 4; p++)
#pragma unroll
                for (int j = 0; j < 4; j++)
#pragma unroll
                    for (int d = 0; d < 4; d++) acc[p][j][d] = 0;
        }
    }
    epilogue(1);
    __syncthreads();

    // ---- coalesced write of final gates ----
    for (int i = tid; i < 32 * 128; i += 256) {
        int r = i >> 7, n = i & 127;
        g_part[blk * 32 + r][n0 + n] = comb[r * 132 + n];
    }
}

// ======================= fused gate / cell elementwise =======================
__global__ void cell_kernel(const float* __restrict__ cx, float* __restrict__ out,
                            const float* a3, const float* a4, const float* a5,
                            const float* a6, const float* a7, const float* a8,
                            const float* a9, const float* a10, const float* a11) {
    int idx = blockIdx.x * blockDim.x + threadIdx.x;
    if (idx >= B_ * H_) return;
    int b = idx >> 10, h = idx & (H_ - 1);
    const float* row = &g_part[b][0];
    float gi = row[h];
    float gj = row[h + H_];
    float gf = row[h + 2 * H_];
    float go = row[h + 3 * H_];
    float v3 = *a3, v4 = *a4, v5 = *a5, v6 = *a6, v7 = *a7;
    float v8 = *a8, v9 = *a9, v10 = *a10, v11 = *a11;

    float fg  = qr8(pact_f(sigmoidf_(gf), v3), v3);
    float ig  = qr8(pact_f(sigmoidf_(gi), v4), v4);
    float act = qr8(pact_f(tanhf(gj),     v5), v5);
    float og  = qr8(pact_f(sigmoidf_(go), v6), v6);
    float gc  = qr8(pact_f(cx[idx] * fg,  v7), v7);
    float ai  = qr8(pact_f(ig * act,      v8), v8);
    float nc  = qr8(pact_f(gc + ai,       v9), v9);
    float ac  = qr8(pact_f(tanhf(nc),     v10), v10);
    float nh  = qr8(pact_f(ac * og,       v11), v11);

    out[idx]           = nh;
    out[B_ * H_ + idx] = nc;
}

// ======================= launch =======================
extern "C" void kernel_launch(void* const* d_in, const int* in_sizes, int n_in,
                              void* d_out, int out_size) {
    const float* input = (const float*)d_in[0];
    const float* hx    = (const float*)d_in[1];
    const float* cx    = (const float*)d_in[2];
    const float* wih   = (const float*)d_in[3];
    const float* whh   = (const float*)d_in[4];
    const float* bih   = (const float*)d_in[5];
    const float* bhh   = (const float*)d_in[6];
    const float* a1    = (const float*)d_in[7];
    const float* a3    = (const float*)d_in[8];
    const float* a4    = (const float*)d_in[9];
    const float* a5    = (const float*)d_in[10];
    const float* a6    = (const float*)d_in[11];
    const float* a7    = (const float*)d_in[12];
    const float* a8    = (const float*)d_in[13];
    const float* a9    = (const float*)d_in[14];
    const float* a10   = (const float*)d_in[15];
    const float* a11   = (const float*)d_in[16];
    float* out = (float*)d_out;

    static int configured = 0;
    if (!configured) {
        cudaFuncSetAttribute(gemm_int8, cudaFuncAttributeMaxDynamicSharedMemorySize,
                             DSM_BYTES);
        configured = 1;
    }

    quant_acts_kernel<<<(2 * (B_ * K_ / 4) + 255) / 256, 256>>>(input, hx, a1, a11);
    quant_w_kernel<<<dim3(NG / 32, K_ / 32, 2), dim3(32, 8)>>>(wih, whh);

    gemm_int8<<<dim3(NG / 128, B_ / 32), 256, DSM_BYTES>>>(a1, a11, bih, bhh);

    cell_kernel<<<(B_ * H_ + 255) / 256, 256>>>(cx, out, a3, a4, a5, a6, a7,
                                                a8, a9, a10, a11);
}

// round 7
// speedup vs baseline: 2.2781x; 2.2781x over previous
#include <cuda_runtime.h>
#include <cuda_bf16.h>
#include <cstdint>

#define B_   4096
#define K_   1024
#define NG   4096    /* 4*H */
#define H_   1024
#define NM   4

#define STAGE_BYTES 32768     /* A 128x64 bf16 (16KB) + B 128x64 bf16 (16KB) */
#define NSTAGES     4
#define DSM_BYTES   (NSTAGES * STAGE_BYTES)   /* 128 KB */
#define CHUNKS_PER_BRANCH 16
#define TOTAL_CHUNKS      32

// ---- scratch (device globals; no runtime allocation) ----
__device__ __nv_bfloat16 g_yA[2][NM][B_][K_];   // 64 MB  bit-plane ints (bf16), K-major
__device__ __nv_bfloat16 g_Wt[2][NG][K_];       // 16 MB  weight ints, transposed [N][K]
__device__ float         g_part[B_][NG];        // 64 MB  final gates

// ======================= small math helpers =======================
__device__ __forceinline__ float pact_f(float x, float a) {
    float ax = fabsf(x);
    float t  = fabsf(ax - a);
    float s  = (x > 0.f) ? 0.5f : ((x < 0.f) ? -0.5f : 0.f);
    return s * ((ax - t) + a);
}
__device__ __forceinline__ float qr8(float x, float r) {
    float xs = x / r;
    xs = fminf(fmaxf(xs, -0.9921875f), 0.9921875f);
    return (rintf(xs * 128.f) * 0.0078125f) * r;
}
__device__ __forceinline__ float sigmoidf_(float x) { return 1.f / (1.f + expf(-x)); }

// ======================= PTX helpers (sm_80-class only) =======================
__device__ __forceinline__ uint32_t s2u(const void* p) {
    uint32_t a;
    asm("{ .reg .u64 t; cvta.to.shared.u64 t, %1; cvt.u32.u64 %0, t; }" : "=r"(a) : "l"(p));
    return a;
}
__device__ __forceinline__ void cp16(uint32_t dst, const void* src) {
    asm volatile("cp.async.cg.shared.global [%0], [%1], 16;" :: "r"(dst), "l"(src) : "memory");
}
__device__ __forceinline__ void ldsm4(uint32_t addr, uint32_t& r0, uint32_t& r1,
                                      uint32_t& r2, uint32_t& r3) {
    asm volatile("ldmatrix.sync.aligned.m8n8.x4.shared.b16 {%0,%1,%2,%3}, [%4];"
                 : "=r"(r0), "=r"(r1), "=r"(r2), "=r"(r3) : "r"(addr));
}
__device__ __forceinline__ void hmma(float* d, const uint32_t* a, const uint32_t* b) {
    asm volatile(
        "mma.sync.aligned.m16n8k16.row.col.f32.bf16.bf16.f32 "
        "{%0,%1,%2,%3}, {%4,%5,%6,%7}, {%8,%9}, {%0,%1,%2,%3};"
        : "+f"(d[0]), "+f"(d[1]), "+f"(d[2]), "+f"(d[3])
        : "r"(a[0]), "r"(a[1]), "r"(a[2]), "r"(a[3]), "r"(b[0]), "r"(b[1]));
}

// ======================= activation bit-split (bf16 planes) =======================
__global__ void quant_acts_kernel(const float* __restrict__ input,
                                  const float* __restrict__ hx,
                                  const float* __restrict__ a1p,
                                  const float* __restrict__ a11p) {
    int idx = blockIdx.x * blockDim.x + threadIdx.x;
    if (idx >= 2 * (B_ * K_ / 4)) return;
    int branch = idx >> 20;               // B_*K_/4 = 2^20
    int r      = idx & ((B_ * K_ / 4) - 1);
    float a = branch ? *a11p : *a1p;
    float4 x4 = ((const float4*)(branch ? hx : input))[r];
    float xs[4] = {x4.x, x4.y, x4.z, x4.w};
    unsigned short o[NM][4];
#pragma unroll
    for (int j = 0; j < 4; j++) {
        float xv = pact_f(xs[j], a) / a;
        float beta = 1.f;
#pragma unroll
        for (int mq = 0; mq < NM; mq++) {
            float s = xv / beta;
            s = fminf(fmaxf(s, -0.9921875f), 0.9921875f);
            float yi = rintf(s * 128.f);       // exact int in [-127,127]
            xv = xv - (yi * 0.0078125f) * beta;
            o[mq][j] = __bfloat16_as_ushort(__float2bfloat16(yi));
            beta *= 0.5f;
        }
    }
#pragma unroll
    for (int mq = 0; mq < NM; mq++) {
        uint2 v;
        v.x = (uint32_t)o[mq][0] | ((uint32_t)o[mq][1] << 16);
        v.y = (uint32_t)o[mq][2] | ((uint32_t)o[mq][3] << 16);
        ((uint2*)&g_yA[branch][mq][0][0])[r] = v;
    }
}

// ======================= weight quant + transpose (bf16) =======================
__global__ void quant_w_kernel(const float* __restrict__ wih,
                               const float* __restrict__ whh) {
    __shared__ float tile[32][33];
    int branch = blockIdx.z;
    const float* w = branch ? whh : wih;
    int n0 = blockIdx.x * 32, k0 = blockIdx.y * 32;
    int tx = threadIdx.x, ty = threadIdx.y;   // 32 x 8
#pragma unroll
    for (int i = 0; i < 4; i++)
        tile[ty + i * 8][tx] = w[(size_t)(k0 + ty + i * 8) * NG + n0 + tx];
    __syncthreads();
#pragma unroll
    for (int i = 0; i < 4; i++) {
        float v = tile[tx][ty + i * 8];
        v = fminf(fmaxf(v, -0.9921875f), 0.9921875f);
        g_Wt[branch][n0 + ty + i * 8][k0 + tx] = __float2bfloat16(rintf(v * 128.f));
    }
}

// ======================= bf16 HMMA GEMM, both branches fused =======================
// CTA tile: M=128 (4 planes x 32 batch rows), N=128. BK=64.
// 8 warps: warp = (mh = warp&1: 16-batch-row half) x (nq = warp>>1: 32-col group).
// Each warp holds ALL 4 planes of its output block -> plane combine in-register.
// grid = 4096 (1D), swizzled so concurrent CTAs share both A (18x) and B (8x) in L2.
__global__ void __launch_bounds__(256, 1) gemm_bf16(const float* __restrict__ a1p,
                                                    const float* __restrict__ a11p,
                                                    const float* __restrict__ bih,
                                                    const float* __restrict__ bhh) {
    extern __shared__ __align__(128) char dsm[];
    __shared__ float comb[32 * 132];
    __shared__ float sbias[2][128];

    const int tid  = threadIdx.x;
    const int lane = tid & 31;
    const int warp = tid >> 5;
    const int mh   = warp & 1;     // 16-row half of the 32 batch rows
    const int nq   = warp >> 1;    // 32-col group (0..3)

    // CTA swizzle: groups of (8 blk) x (32 n-blocks)
    const int g     = blockIdx.x;
    const int group = g >> 8;                   // 0..15
    const int rem   = g & 255;
    const int blk   = (group << 3) | (rem & 7); // 0..127
    const int n0    = (rem >> 3) * 128;         // 0..3968

    if (tid < 128) {
        float v0 = fminf(fmaxf(bih[n0 + tid], -0.9921875f), 0.9921875f);
        sbias[0][tid] = rintf(v0 * 128.f);
        float v1 = fminf(fmaxf(bhh[n0 + tid], -0.9921875f), 0.9921875f);
        sbias[1][tid] = rintf(v1 * 128.f);
    }
    const float a1v  = *a1p;
    const float a11v = *a11p;

    const uint32_t smem = s2u(dsm);

    // ---- cp.async slots: 4 A-chunks + 4 B-chunks of 16B per thread per stage ----
    // tile rows are 128 bytes = 8 x 16B chunks; swizzle: chunk' = chunk ^ (row&7)
    uint32_t a_src[4], a_dst[4], b_src[4], b_dst[4];
#pragma unroll
    for (int i = 0; i < 4; i++) {
        int s   = tid + 256 * i;               // 0..1023
        int row = s >> 3, ch = s & 7;
        int plane = row >> 5;
        int brow  = blk * 32 + (row & 31);
        a_src[i] = (uint32_t)(((plane * B_ + brow) * K_ + ch * 8) * 2);
        a_dst[i] = (uint32_t)(row * 128 + ((ch ^ (row & 7)) << 4));
        b_src[i] = (uint32_t)(((n0 + row) * K_ + ch * 8) * 2);
        b_dst[i] = (uint32_t)(16384 + row * 128 + ((ch ^ (row & 7)) << 4));
    }
    const char* gA = (const char*)&g_yA[0][0][0][0];
    const char* gB = (const char*)&g_Wt[0][0][0];

    // ---- ldmatrix lane constants ----
    const int m   = lane >> 3;          // matrix index within ldsm.x4
    const int rr  = lane & 7;
    const int akh = m >> 1;             // A: k-half (16B) selector
    const int bkh = m & 1;              // B: k-half selector
    uint32_t aoffx[4];                  // per plane, row-swizzle folded into bits[4:6]
#pragma unroll
    for (int p = 0; p < 4; p++) {
        int row = p * 32 + mh * 16 + (m & 1) * 8 + rr;
        aoffx[p] = (uint32_t)(row * 128) | ((uint32_t)(row & 7) << 4);
    }
    uint32_t boffx[2];
#pragma unroll
    for (int t = 0; t < 2; t++) {
        int row = nq * 32 + t * 16 + (m >> 1) * 8 + rr;
        boffx[t] = (uint32_t)(16384 + row * 128) | ((uint32_t)(row & 7) << 4);
    }

    float acc[4][4][4];                 // [plane][n8-group][frag]
#pragma unroll
    for (int p = 0; p < 4; p++)
#pragma unroll
        for (int j = 0; j < 4; j++)
#pragma unroll
            for (int d = 0; d < 4; d++) acc[p][j][d] = 0.f;

    auto load_stage = [&](int c, int stage) {
        int br = c >> 4;
        uint32_t k = (uint32_t)(c & 15) * 128;          // 64 bf16 = 128B per chunk
        uint32_t st = smem + (uint32_t)stage * STAGE_BYTES;
        const char* A  = gA + (size_t)br * ((size_t)NM * B_ * K_ * 2) + k;
        const char* Bp = gB + (size_t)br * ((size_t)NG * K_ * 2) + k;
#pragma unroll
        for (int i = 0; i < 4; i++) {
            cp16(st + a_dst[i], A + a_src[i]);
            cp16(st + b_dst[i], Bp + b_src[i]);
        }
    };

    auto compute_stage = [&](int stage) {
        uint32_t st = smem + (uint32_t)stage * STAGE_BYTES;
#pragma unroll
        for (int s = 0; s < 4; s++) {          // four k16 steps per BK=64
            uint32_t aks = (uint32_t)(s * 2 + akh) << 4;
            uint32_t bks = (uint32_t)(s * 2 + bkh) << 4;
            uint32_t a[4][4];
#pragma unroll
            for (int p = 0; p < 4; p++)
                ldsm4((st + aoffx[p]) ^ aks, a[p][0], a[p][1], a[p][2], a[p][3]);
#pragma unroll
            for (int t = 0; t < 2; t++) {
                uint32_t b[4];
                ldsm4((st + boffx[t]) ^ bks, b[0], b[1], b[2], b[3]);
#pragma unroll
                for (int p = 0; p < 4; p++) {
                    hmma(acc[p][2 * t],     a[p], &b[0]);
                    hmma(acc[p][2 * t + 1], a[p], &b[2]);
                }
            }
        }
    };

    // plane combine fully in-register: each output element owned by ONE thread
    auto epilogue = [&](int br) {
        float av = br ? a11v : a1v;
        float sc0 = av * 0.0078125f;
#pragma unroll
        for (int j = 0; j < 4; j++) {
            int nnb = nq * 32 + j * 8 + (lane & 3) * 2;
#pragma unroll
            for (int d = 0; d < 4; d++) {
                int nn = nnb + (d & 1);
                int rw = mh * 16 + (lane >> 2) + (d >> 1) * 8;
                float bz = sbias[br][nn];
                float v = 0.f;
#pragma unroll
                for (int p = 0; p < 4; p++) {
                    float t = acc[p][j][d] * 0.0078125f + bz;
                    float q = fminf(fmaxf(rintf(t), -127.f), 127.f);
                    v += q * (sc0 / (float)(1 << p));
                }
                float* dst = &comb[rw * 132 + nn];
                if (br == 0) *dst = v; else *dst += v;
            }
        }
    };

    // ---- pipeline: 4 stages, 32 chunks (branch = chunk>>4) ----
#pragma unroll
    for (int c = 0; c < NSTAGES - 1; c++) {
        load_stage(c, c);
        asm volatile("cp.async.commit_group;" ::: "memory");
    }
    int ls = NSTAGES - 1;
    int cs = 0;
    for (int c = 0; c < TOTAL_CHUNKS; c++) {
        asm volatile("cp.async.wait_group %0;" :: "n"(NSTAGES - 2) : "memory");
        __syncthreads();
        if (c + NSTAGES - 1 < TOTAL_CHUNKS) load_stage(c + NSTAGES - 1, ls);
        asm volatile("cp.async.commit_group;" ::: "memory");
        if (++ls == NSTAGES) ls = 0;
        compute_stage(cs);
        if (++cs == NSTAGES) cs = 0;
        if (c == CHUNKS_PER_BRANCH - 1) {
            epilogue(0);
#pragma unroll
            for (int p = 0; p < 4; p++)
#pragma unroll
                for (int j = 0; j < 4; j++)
#pragma unroll
                    for (int d = 0; d < 4; d++) acc[p][j][d] = 0.f;
        }
    }
    epilogue(1);
    __syncthreads();

    // ---- coalesced write of final gates ----
    for (int i = tid; i < 32 * 128; i += 256) {
        int r = i >> 7, n = i & 127;
        g_part[blk * 32 + r][n0 + n] = comb[r * 132 + n];
    }
}

// ======================= fused gate / cell elementwise =======================
__global__ void cell_kernel(const float* __restrict__ cx, float* __restrict__ out,
                            const float* a3, const float* a4, const float* a5,
                            const float* a6, const float* a7, const float* a8,
                            const float* a9, const float* a10, const float* a11) {
    int idx = blockIdx.x * blockDim.x + threadIdx.x;
    if (idx >= B_ * H_) return;
    int b = idx >> 10, h = idx & (H_ - 1);
    const float* row = &g_part[b][0];
    float gi = row[h];
    float gj = row[h + H_];
    float gf = row[h + 2 * H_];
    float go = row[h + 3 * H_];
    float v3 = *a3, v4 = *a4, v5 = *a5, v6 = *a6, v7 = *a7;
    float v8 = *a8, v9 = *a9, v10 = *a10, v11 = *a11;

    float fg  = qr8(pact_f(sigmoidf_(gf), v3), v3);
    float ig  = qr8(pact_f(sigmoidf_(gi), v4), v4);
    float act = qr8(pact_f(tanhf(gj),     v5), v5);
    float og  = qr8(pact_f(sigmoidf_(go), v6), v6);
    float gc  = qr8(pact_f(cx[idx] * fg,  v7), v7);
    float ai  = qr8(pact_f(ig * act,      v8), v8);
    float nc  = qr8(pact_f(gc + ai,       v9), v9);
    float ac  = qr8(pact_f(tanhf(nc),     v10), v10);
    float nh  = qr8(pact_f(ac * og,       v11), v11);

    out[idx]           = nh;
    out[B_ * H_ + idx] = nc;
}

// ======================= launch =======================
extern "C" void kernel_launch(void* const* d_in, const int* in_sizes, int n_in,
                              void* d_out, int out_size) {
    const float* input = (const float*)d_in[0];
    const float* hx    = (const float*)d_in[1];
    const float* cx    = (const float*)d_in[2];
    const float* wih   = (const float*)d_in[3];
    const float* whh   = (const float*)d_in[4];
    const float* bih   = (const float*)d_in[5];
    const float* bhh   = (const float*)d_in[6];
    const float* a1    = (const float*)d_in[7];
    const float* a3    = (const float*)d_in[8];
    const float* a4    = (const float*)d_in[9];
    const float* a5    = (const float*)d_in[10];
    const float* a6    = (const float*)d_in[11];
    const float* a7    = (const float*)d_in[12];
    const float* a8    = (const float*)d_in[13];
    const float* a9    = (const float*)d_in[14];
    const float* a10   = (const float*)d_in[15];
    const float* a11   = (const float*)d_in[16];
    float* out = (float*)d_out;

    static int configured = 0;
    if (!configured) {
        cudaFuncSetAttribute(gemm_bf16, cudaFuncAttributeMaxDynamicSharedMemorySize,
                             DSM_BYTES);
        configured = 1;
    }

    quant_acts_kernel<<<(2 * (B_ * K_ / 4) + 255) / 256, 256>>>(input, hx, a1, a11);
    quant_w_kernel<<<dim3(NG / 32, K_ / 32, 2), dim3(32, 8)>>>(wih, whh);

    gemm_bf16<<<4096, 256, DSM_BYTES>>>(a1, a11, bih, bhh);

    cell_kernel<<<(B_ * H_ + 255) / 256, 256>>>(cx, out, a3, a4, a5, a6, a7,
                                                a8, a9, a10, a11);
}

// round 8
// speedup vs baseline: 2.5005x; 1.0976x over previous
#include <cuda_runtime.h>
#include <cuda_bf16.h>
#include <cstdint>

#define B_   4096
#define K_   1024
#define NG   4096    /* 4*H */
#define H_   1024
#define NM   4

#define STAGE_BYTES 49152     /* A 128x64 bf16 (16KB) + B 256x64 bf16 (32KB) */
#define NSTAGES     3
#define DSM_BYTES   (NSTAGES * STAGE_BYTES)   /* 144 KB */
#define CHUNKS_PER_BRANCH 16
#define TOTAL_CHUNKS      32

// ---- scratch (device globals; no runtime allocation) ----
__device__ __nv_bfloat16 g_yA[2][NM][B_][K_];   // 64 MB  bit-plane ints (bf16), K-major
__device__ __nv_bfloat16 g_Wt[2][NG][K_];       // 16 MB  weight ints, transposed [N][K]
__device__ float         g_part[B_][NG];        // 64 MB  final gates

// ======================= small math helpers =======================
__device__ __forceinline__ float pact_f(float x, float a) {
    float ax = fabsf(x);
    float t  = fabsf(ax - a);
    float s  = (x > 0.f) ? 0.5f : ((x < 0.f) ? -0.5f : 0.f);
    return s * ((ax - t) + a);
}
__device__ __forceinline__ float qr8(float x, float r) {
    float xs = x / r;
    xs = fminf(fmaxf(xs, -0.9921875f), 0.9921875f);
    return (rintf(xs * 128.f) * 0.0078125f) * r;
}
__device__ __forceinline__ float sigmoidf_(float x) { return 1.f / (1.f + expf(-x)); }
__device__ __forceinline__ float sigmoidf_fast(float x) { return 1.f / (1.f + __expf(-x)); }

// ======================= PTX helpers (sm_80-class only) =======================
__device__ __forceinline__ uint32_t s2u(const void* p) {
    uint32_t a;
    asm("{ .reg .u64 t; cvta.to.shared.u64 t, %1; cvt.u32.u64 %0, t; }" : "=r"(a) : "l"(p));
    return a;
}
__device__ __forceinline__ void cp16(uint32_t dst, const void* src) {
    asm volatile("cp.async.cg.shared.global [%0], [%1], 16;" :: "r"(dst), "l"(src) : "memory");
}
__device__ __forceinline__ void ldsm4(uint32_t addr, uint32_t& r0, uint32_t& r1,
                                      uint32_t& r2, uint32_t& r3) {
    asm volatile("ldmatrix.sync.aligned.m8n8.x4.shared.b16 {%0,%1,%2,%3}, [%4];"
                 : "=r"(r0), "=r"(r1), "=r"(r2), "=r"(r3) : "r"(addr));
}
__device__ __forceinline__ void hmma(float* d, const uint32_t* a, const uint32_t* b) {
    asm volatile(
        "mma.sync.aligned.m16n8k16.row.col.f32.bf16.bf16.f32 "
        "{%0,%1,%2,%3}, {%4,%5,%6,%7}, {%8,%9}, {%0,%1,%2,%3};"
        : "+f"(d[0]), "+f"(d[1]), "+f"(d[2]), "+f"(d[3])
        : "r"(a[0]), "r"(a[1]), "r"(a[2]), "r"(a[3]), "r"(b[0]), "r"(b[1]));
}

// ======================= activation bit-split (bf16 planes) =======================
__global__ void quant_acts_kernel(const float* __restrict__ input,
                                  const float* __restrict__ hx,
                                  const float* __restrict__ a1p,
                                  const float* __restrict__ a11p) {
    int idx = blockIdx.x * blockDim.x + threadIdx.x;
    if (idx >= 2 * (B_ * K_ / 4)) return;
    int branch = idx >> 20;               // B_*K_/4 = 2^20
    int r      = idx & ((B_ * K_ / 4) - 1);
    float a = branch ? *a11p : *a1p;
    float4 x4 = ((const float4*)(branch ? hx : input))[r];
    float xs[4] = {x4.x, x4.y, x4.z, x4.w};
    unsigned short o[NM][4];
#pragma unroll
    for (int j = 0; j < 4; j++) {
        float xv = pact_f(xs[j], a) / a;
        float beta = 1.f;
#pragma unroll
        for (int mq = 0; mq < NM; mq++) {
            float s = xv / beta;
            s = fminf(fmaxf(s, -0.9921875f), 0.9921875f);
            float yi = rintf(s * 128.f);       // exact int in [-127,127]
            xv = xv - (yi * 0.0078125f) * beta;
            o[mq][j] = __bfloat16_as_ushort(__float2bfloat16(yi));
            beta *= 0.5f;
        }
    }
#pragma unroll
    for (int mq = 0; mq < NM; mq++) {
        uint2 v;
        v.x = (uint32_t)o[mq][0] | ((uint32_t)o[mq][1] << 16);
        v.y = (uint32_t)o[mq][2] | ((uint32_t)o[mq][3] << 16);
        ((uint2*)&g_yA[branch][mq][0][0])[r] = v;
    }
}

// ======================= weight quant + transpose (bf16) =======================
__global__ void quant_w_kernel(const float* __restrict__ wih,
                               const float* __restrict__ whh) {
    __shared__ float tile[32][33];
    int branch = blockIdx.z;
    const float* w = branch ? whh : wih;
    int n0 = blockIdx.x * 32, k0 = blockIdx.y * 32;
    int tx = threadIdx.x, ty = threadIdx.y;   // 32 x 8
#pragma unroll
    for (int i = 0; i < 4; i++)
        tile[ty + i * 8][tx] = w[(size_t)(k0 + ty + i * 8) * NG + n0 + tx];
    __syncthreads();
#pragma unroll
    for (int i = 0; i < 4; i++) {
        float v = tile[tx][ty + i * 8];
        v = fminf(fmaxf(v, -0.9921875f), 0.9921875f);
        g_Wt[branch][n0 + ty + i * 8][k0 + tx] = __float2bfloat16(rintf(v * 128.f));
    }
}

// ======================= bf16 HMMA GEMM, both branches fused =======================
// CTA tile: M=128 (4 planes x 32 batch rows), N=256. BK=64.
// 8 warps: warp = (mh = warp&1: 16-batch-row half) x (nq = warp>>1: 64-col group).
// Each warp holds ALL 4 planes of its 16x64 block -> plane combine in-register.
// Per k16-step per warp: 8 LDSM.x4 feed 32 HMMA (1:4) -> tensor-bound.
// grid = 2048 (1D), swizzled: 8 blk x 16 n-blocks concurrent -> A 16x, B 8x L2 reuse.
__global__ void __launch_bounds__(256, 1) gemm_bf16(const float* __restrict__ a1p,
                                                    const float* __restrict__ a11p,
                                                    const float* __restrict__ bih,
                                                    const float* __restrict__ bhh) {
    extern __shared__ __align__(128) char dsm[];
    __shared__ float comb[32 * 260];
    __shared__ float sbias[2][256];

    const int tid  = threadIdx.x;
    const int lane = tid & 31;
    const int warp = tid >> 5;
    const int mh   = warp & 1;     // 16-row half of the 32 batch rows
    const int nq   = warp >> 1;    // 64-col group (0..3)

    // CTA swizzle: groups of (8 blk) x (16 n-blocks)
    const int g     = blockIdx.x;
    const int group = g >> 7;                   // 0..15
    const int rem   = g & 127;
    const int blk   = (group << 3) | (rem & 7); // 0..127
    const int n0    = (rem >> 3) * 256;         // 0..3840

    {
        float v0 = fminf(fmaxf(bih[n0 + tid], -0.9921875f), 0.9921875f);
        sbias[0][tid] = rintf(v0 * 128.f);
        float v1 = fminf(fmaxf(bhh[n0 + tid], -0.9921875f), 0.9921875f);
        sbias[1][tid] = rintf(v1 * 128.f);
    }
    const float a1v  = *a1p;
    const float a11v = *a11p;

    const uint32_t smem = s2u(dsm);

    // ---- cp.async slots: 4 A-chunks + 8 B-chunks of 16B per thread per stage ----
    // tile rows are 128 bytes = 8 x 16B chunks; swizzle: chunk' = chunk ^ (row&7)
    uint32_t a_src[4], a_dst[4], b_src[8], b_dst[8];
#pragma unroll
    for (int i = 0; i < 4; i++) {
        int s   = tid + 256 * i;               // 0..1023
        int row = s >> 3, ch = s & 7;
        int plane = row >> 5;
        int brow  = blk * 32 + (row & 31);
        a_src[i] = (uint32_t)(((plane * B_ + brow) * K_ + ch * 8) * 2);
        a_dst[i] = (uint32_t)(row * 128 + ((ch ^ (row & 7)) << 4));
    }
#pragma unroll
    for (int i = 0; i < 8; i++) {
        int s   = tid + 256 * i;               // 0..2047
        int row = s >> 3, ch = s & 7;
        b_src[i] = (uint32_t)(((n0 + row) * K_ + ch * 8) * 2);
        b_dst[i] = (uint32_t)(16384 + row * 128 + ((ch ^ (row & 7)) << 4));
    }
    const char* gA = (const char*)&g_yA[0][0][0][0];
    const char* gB = (const char*)&g_Wt[0][0][0];

    // ---- ldmatrix lane constants ----
    const int m   = lane >> 3;          // matrix index within ldsm.x4
    const int rr  = lane & 7;
    const int akh = m >> 1;             // A: k-half (16B) selector
    const int bkh = m & 1;              // B: k-half selector
    uint32_t aoffx[4];                  // per plane, row-swizzle folded into bits[4:6]
#pragma unroll
    for (int p = 0; p < 4; p++) {
        int row = p * 32 + mh * 16 + (m & 1) * 8 + rr;
        aoffx[p] = (uint32_t)(row * 128) | ((uint32_t)(row & 7) << 4);
    }
    uint32_t boffx[4];
#pragma unroll
    for (int t = 0; t < 4; t++) {
        int row = nq * 64 + t * 16 + (m >> 1) * 8 + rr;
        boffx[t] = (uint32_t)(16384 + row * 128) | ((uint32_t)(row & 7) << 4);
    }

    float acc[4][8][4];                 // [plane][n8-group][frag]
#pragma unroll
    for (int p = 0; p < 4; p++)
#pragma unroll
        for (int j = 0; j < 8; j++)
#pragma unroll
            for (int d = 0; d < 4; d++) acc[p][j][d] = 0.f;

    auto load_stage = [&](int c, int stage) {
        int br = c >> 4;
        uint32_t k = (uint32_t)(c & 15) * 128;          // 64 bf16 = 128B per chunk
        uint32_t st = smem + (uint32_t)stage * STAGE_BYTES;
        const char* A  = gA + (size_t)br * ((size_t)NM * B_ * K_ * 2) + k;
        const char* Bp = gB + (size_t)br * ((size_t)NG * K_ * 2) + k;
#pragma unroll
        for (int i = 0; i < 4; i++) cp16(st + a_dst[i], A + a_src[i]);
#pragma unroll
        for (int i = 0; i < 8; i++) cp16(st + b_dst[i], Bp + b_src[i]);
    };

    auto compute_stage = [&](int stage) {
        uint32_t st = smem + (uint32_t)stage * STAGE_BYTES;
#pragma unroll
        for (int s = 0; s < 4; s++) {          // four k16 steps per BK=64
            uint32_t aks = (uint32_t)(s * 2 + akh) << 4;
            uint32_t bks = (uint32_t)(s * 2 + bkh) << 4;
            uint32_t a[4][4];
#pragma unroll
            for (int p = 0; p < 4; p++)
                ldsm4((st + aoffx[p]) ^ aks, a[p][0], a[p][1], a[p][2], a[p][3]);
#pragma unroll
            for (int t = 0; t < 4; t++) {
                uint32_t b[4];
                ldsm4((st + boffx[t]) ^ bks, b[0], b[1], b[2], b[3]);
#pragma unroll
                for (int p = 0; p < 4; p++) {
                    hmma(acc[p][2 * t],     a[p], &b[0]);
                    hmma(acc[p][2 * t + 1], a[p], &b[2]);
                }
            }
        }
    };

    // plane combine fully in-register: each output element owned by ONE thread
    auto epilogue = [&](int br) {
        float av = br ? a11v : a1v;
        float sc0 = av * 0.0078125f;
#pragma unroll
        for (int j = 0; j < 8; j++) {
            int nnb = nq * 64 + j * 8 + (lane & 3) * 2;
#pragma unroll
            for (int d = 0; d < 4; d++) {
                int nn = nnb + (d & 1);
                int rw = mh * 16 + (lane >> 2) + (d >> 1) * 8;
                float bz = sbias[br][nn];
                float v = 0.f;
#pragma unroll
                for (int p = 0; p < 4; p++) {
                    float t = acc[p][j][d] * 0.0078125f + bz;
                    float q = fminf(fmaxf(rintf(t), -127.f), 127.f);
                    v += q * (sc0 / (float)(1 << p));
                }
                float* dst = &comb[rw * 260 + nn];
                if (br == 0) *dst = v; else *dst += v;
            }
        }
    };

    // ---- pipeline: 3 stages, 32 chunks (branch = chunk>>4) ----
#pragma unroll
    for (int c = 0; c < NSTAGES - 1; c++) {
        load_stage(c, c);
        asm volatile("cp.async.commit_group;" ::: "memory");
    }
    int ls = NSTAGES - 1;
    int cs = 0;
    for (int c = 0; c < TOTAL_CHUNKS; c++) {
        asm volatile("cp.async.wait_group %0;" :: "n"(NSTAGES - 2) : "memory");
        __syncthreads();
        if (c + NSTAGES - 1 < TOTAL_CHUNKS) load_stage(c + NSTAGES - 1, ls);
        asm volatile("cp.async.commit_group;" ::: "memory");
        if (++ls == NSTAGES) ls = 0;
        compute_stage(cs);
        if (++cs == NSTAGES) cs = 0;
        if (c == CHUNKS_PER_BRANCH - 1) {
            epilogue(0);
#pragma unroll
            for (int p = 0; p < 4; p++)
#pragma unroll
                for (int j = 0; j < 8; j++)
#pragma unroll
                    for (int d = 0; d < 4; d++) acc[p][j][d] = 0.f;
        }
    }
    epilogue(1);
    __syncthreads();

    // ---- coalesced write of final gates ----
    for (int i = tid; i < 32 * 256; i += 256) {
        int r = i >> 8, n = i & 255;
        g_part[blk * 32 + r][n0 + n] = comb[r * 260 + n];
    }
}

// ======================= fused gate / cell elementwise =======================
__global__ void cell_kernel(const float* __restrict__ cx, float* __restrict__ out,
                            const float* a3, const float* a4, const float* a5,
                            const float* a6, const float* a7, const float* a8,
                            const float* a9, const float* a10, const float* a11) {
    int idx = blockIdx.x * blockDim.x + threadIdx.x;
    if (idx >= B_ * H_) return;
    int b = idx >> 10, h = idx & (H_ - 1);
    const float* row = &g_part[b][0];
    float gi = row[h];
    float gj = row[h + H_];
    float gf = row[h + 2 * H_];
    float go = row[h + 3 * H_];
    float v3 = *a3, v4 = *a4, v5 = *a5, v6 = *a6, v7 = *a7;
    float v8 = *a8, v9 = *a9, v10 = *a10, v11 = *a11;

    float fg  = qr8(pact_f(sigmoidf_fast(gf), v3), v3);
    float ig  = qr8(pact_f(sigmoidf_fast(gi), v4), v4);
    float act = qr8(pact_f(tanhf(gj),     v5), v5);
    float og  = qr8(pact_f(sigmoidf_fast(go), v6), v6);
    float gc  = qr8(pact_f(cx[idx] * fg,  v7), v7);
    float ai  = qr8(pact_f(ig * act,      v8), v8);
    float nc  = qr8(pact_f(gc + ai,       v9), v9);
    float ac  = qr8(pact_f(tanhf(nc),     v10), v10);
    float nh  = qr8(pact_f(ac * og,       v11), v11);

    out[idx]           = nh;
    out[B_ * H_ + idx] = nc;
}

// ======================= launch =======================
extern "C" void kernel_launch(void* const* d_in, const int* in_sizes, int n_in,
                              void* d_out, int out_size) {
    const float* input = (const float*)d_in[0];
    const float* hx    = (const float*)d_in[1];
    const float* cx    = (const float*)d_in[2];
    const float* wih   = (const float*)d_in[3];
    const float* whh   = (const float*)d_in[4];
    const float* bih   = (const float*)d_in[5];
    const float* bhh   = (const float*)d_in[6];
    const float* a1    = (const float*)d_in[7];
    const float* a3    = (const float*)d_in[8];
    const float* a4    = (const float*)d_in[9];
    const float* a5    = (const float*)d_in[10];
    const float* a6    = (const float*)d_in[11];
    const float* a7    = (const float*)d_in[12];
    const float* a8    = (const float*)d_in[13];
    const float* a9    = (const float*)d_in[14];
    const float* a10   = (const float*)d_in[15];
    const float* a11   = (const float*)d_in[16];
    float* out = (float*)d_out;

    static int configured = 0;
    if (!configured) {
        cudaFuncSetAttribute(gemm_bf16, cudaFuncAttributeMaxDynamicSharedMemorySize,
                             DSM_BYTES);
        configured = 1;
    }

    quant_acts_kernel<<<(2 * (B_ * K_ / 4) + 255) / 256, 256>>>(input, hx, a1, a11);
    quant_w_kernel<<<dim3(NG / 32, K_ / 32, 2), dim3(32, 8)>>>(wih, whh);

    gemm_bf16<<<2048, 256, DSM_BYTES>>>(a1, a11, bih, bhh);

    cell_kernel<<<(B_ * H_ + 255) / 256, 256>>>(cx, out, a3, a4, a5, a6, a7,
                                                a8, a9, a10, a11);
}

// round 9
// speedup vs baseline: 2.9332x; 1.1731x over previous
#include <cuda_runtime.h>
#include <cuda_bf16.h>
#include <cstdint>

#define B_   4096
#define K_   1024
#define NG   4096    /* 4*H */
#define H_   1024
#define NM   4

#define STAGE_BYTES 32768     /* A 128x64 bf16 (16KB) + B 128x64 bf16 (16KB) */
#define NSTAGES     3
#define DSM_BYTES   (NSTAGES * STAGE_BYTES)   /* 96 KB -> 2 CTAs/SM */
#define CHUNKS_PER_BRANCH 16
#define TOTAL_CHUNKS      32

// ---- scratch (device globals; no runtime allocation) ----
__device__ __nv_bfloat16 g_yA[2][NM][B_][K_];   // 64 MB  bit-plane ints (bf16), K-major
__device__ __nv_bfloat16 g_Wt[2][NG][K_];       // 16 MB  weight ints, transposed [N][K]
__device__ float         g_part[B_][NG];        // 64 MB  final gates

// ======================= small math helpers =======================
__device__ __forceinline__ float pact_f(float x, float a) {
    float ax = fabsf(x);
    float t  = fabsf(ax - a);
    float s  = (x > 0.f) ? 0.5f : ((x < 0.f) ? -0.5f : 0.f);
    return s * ((ax - t) + a);
}
__device__ __forceinline__ float qr8(float x, float r) {
    float xs = x / r;
    xs = fminf(fmaxf(xs, -0.9921875f), 0.9921875f);
    return (rintf(xs * 128.f) * 0.0078125f) * r;
}
__device__ __forceinline__ float sigmoidf_fast(float x) { return 1.f / (1.f + __expf(-x)); }
// saturation-safe fast tanh: exp(2x)=inf -> 1, exp(2x)=0 -> -1
__device__ __forceinline__ float tanhf_fast(float x) {
    return 1.f - 2.f / (__expf(2.f * x) + 1.f);
}

// ======================= PTX helpers (sm_80-class only) =======================
__device__ __forceinline__ uint32_t s2u(const void* p) {
    uint32_t a;
    asm("{ .reg .u64 t; cvta.to.shared.u64 t, %1; cvt.u32.u64 %0, t; }" : "=r"(a) : "l"(p));
    return a;
}
__device__ __forceinline__ void cp16(uint32_t dst, const void* src) {
    asm volatile("cp.async.cg.shared.global [%0], [%1], 16;" :: "r"(dst), "l"(src) : "memory");
}
__device__ __forceinline__ void ldsm4(uint32_t addr, uint32_t& r0, uint32_t& r1,
                                      uint32_t& r2, uint32_t& r3) {
    asm volatile("ldmatrix.sync.aligned.m8n8.x4.shared.b16 {%0,%1,%2,%3}, [%4];"
                 : "=r"(r0), "=r"(r1), "=r"(r2), "=r"(r3) : "r"(addr));
}
__device__ __forceinline__ void hmma(float* d, const uint32_t* a, const uint32_t* b) {
    asm volatile(
        "mma.sync.aligned.m16n8k16.row.col.f32.bf16.bf16.f32 "
        "{%0,%1,%2,%3}, {%4,%5,%6,%7}, {%8,%9}, {%0,%1,%2,%3};"
        : "+f"(d[0]), "+f"(d[1]), "+f"(d[2]), "+f"(d[3])
        : "r"(a[0]), "r"(a[1]), "r"(a[2]), "r"(a[3]), "r"(b[0]), "r"(b[1]));
}

// ======================= fused prep: bit-split + weight quant/transpose ============
__global__ void prep_kernel(const float* __restrict__ input,
                            const float* __restrict__ hx,
                            const float* __restrict__ wih,
                            const float* __restrict__ whh,
                            const float* __restrict__ a1p,
                            const float* __restrict__ a11p) {
    __shared__ float tile[32][33];
    int bx  = blockIdx.x;
    int tid = threadIdx.x;
    if (bx < 8192) {
        // ---- activation bit-split ----
        int idx = bx * 256 + tid;
        int branch = idx >> 20;               // B_*K_/4 = 2^20
        int r      = idx & ((B_ * K_ / 4) - 1);
        float a = branch ? *a11p : *a1p;
        float4 x4 = ((const float4*)(branch ? hx : input))[r];
        float xs[4] = {x4.x, x4.y, x4.z, x4.w};
        unsigned short o[NM][4];
#pragma unroll
        for (int j = 0; j < 4; j++) {
            float xv = pact_f(xs[j], a) / a;
            float beta = 1.f;
#pragma unroll
            for (int mq = 0; mq < NM; mq++) {
                float s = xv / beta;
                s = fminf(fmaxf(s, -0.9921875f), 0.9921875f);
                float yi = rintf(s * 128.f);       // exact int in [-127,127]
                xv = xv - (yi * 0.0078125f) * beta;
                o[mq][j] = __bfloat16_as_ushort(__float2bfloat16(yi));
                beta *= 0.5f;
            }
        }
#pragma unroll
        for (int mq = 0; mq < NM; mq++) {
            uint2 v;
            v.x = (uint32_t)o[mq][0] | ((uint32_t)o[mq][1] << 16);
            v.y = (uint32_t)o[mq][2] | ((uint32_t)o[mq][3] << 16);
            ((uint2*)&g_yA[branch][mq][0][0])[r] = v;
        }
    } else {
        // ---- weight quant + transpose, one 32x32 tile per block ----
        int wb     = bx - 8192;               // 0..8191
        int branch = wb >> 12;                // 4096 tiles per branch
        int rem    = wb & 4095;
        int n0 = (rem & 127) * 32;
        int k0 = (rem >> 7) * 32;
        const float* w = branch ? whh : wih;
        int tx = tid & 31, ty = tid >> 5;     // 32 x 8
#pragma unroll
        for (int i = 0; i < 4; i++)
            tile[ty + i * 8][tx] = w[(size_t)(k0 + ty + i * 8) * NG + n0 + tx];
        __syncthreads();
#pragma unroll
        for (int i = 0; i < 4; i++) {
            float v = tile[tx][ty + i * 8];
            v = fminf(fmaxf(v, -0.9921875f), 0.9921875f);
            g_Wt[branch][n0 + ty + i * 8][k0 + tx] = __float2bfloat16(rintf(v * 128.f));
        }
    }
}

// ======================= bf16 HMMA GEMM, both branches fused =======================
// CTA: 128 threads, tile M=128 (4 planes x 32 batch rows) x N=128. BK=64.
// 4 warps: warp = (mh = warp&1: 16-row half) x (nq = warp>>1: 64-col group).
// Warp holds ALL 4 planes of its 16x64 block -> plane combine in-register.
// 96KB dyn smem -> 2 CTAs/SM -> 4 warps/SMSP to hide sync/ldsm latency.
// Plane-combined partials go straight to g_part (no smem comb buffer).
// grid = 4096 (128 blk x 32 n-blocks), swizzled 16x16 groups for L2 reuse.
__global__ void __launch_bounds__(128, 2) gemm_bf16(const float* __restrict__ a1p,
                                                    const float* __restrict__ a11p,
                                                    const float* __restrict__ bih,
                                                    const float* __restrict__ bhh) {
    extern __shared__ __align__(128) char dsm[];
    __shared__ float sbias[2][128];

    const int tid  = threadIdx.x;
    const int lane = tid & 31;
    const int warp = tid >> 5;
    const int mh   = warp & 1;     // 16-row half of the 32 batch rows
    const int nq   = warp >> 1;    // 64-col group (0..1)

    // CTA swizzle: 16 groups of (16 blk x 16 n-blocks)
    const int g   = blockIdx.x;
    const int bg  = (g >> 8) & 7;               // blk-group 0..7
    const int ng  = g >> 11;                    // n-group 0..1
    const int rem = g & 255;
    const int blk = bg * 16 + (rem & 15);       // 0..127
    const int n0  = (ng * 16 + (rem >> 4)) * 128;  // 0..3968

    {
        float v0 = fminf(fmaxf(bih[n0 + tid], -0.9921875f), 0.9921875f);
        sbias[0][tid] = rintf(v0 * 128.f);
        float v1 = fminf(fmaxf(bhh[n0 + tid], -0.9921875f), 0.9921875f);
        sbias[1][tid] = rintf(v1 * 128.f);
    }
    const float a1v  = *a1p;
    const float a11v = *a11p;

    const uint32_t smem = s2u(dsm);

    // ---- cp.async slots: 8 A + 8 B 16B-chunks per thread per stage ----
    // rows are 128B = 8 chunks; swizzle: chunk' = chunk ^ (row&7)
    const int row0 = tid >> 3, ch0 = tid & 7;
    uint32_t a_srcs[8];
#pragma unroll
    for (int i = 0; i < 8; i++) {
        int row   = row0 + 16 * i;
        int plane = row >> 5;
        int brow  = blk * 32 + (row & 31);
        a_srcs[i] = (uint32_t)(((plane * B_ + brow) * K_ + ch0 * 8) * 2);
    }
    const uint32_t a_dst0 = (uint32_t)(row0 * 128 + ((ch0 ^ (row0 & 7)) << 4));
    const uint32_t b_src0 = (uint32_t)(((n0 + row0) * K_ + ch0 * 8) * 2);
    const uint32_t b_dst0 = (uint32_t)(16384 + row0 * 128 + ((ch0 ^ (row0 & 7)) << 4));
    const char* gA = (const char*)&g_yA[0][0][0][0];
    const char* gB = (const char*)&g_Wt[0][0][0];

    // ---- ldmatrix lane constants ----
    const int m   = lane >> 3;          // matrix index within ldsm.x4
    const int rr  = lane & 7;
    const int akh = m >> 1;             // A: k-half (16B) selector
    const int bkh = m & 1;              // B: k-half selector
    uint32_t aoffx[4];                  // per plane, row-swizzle folded into bits[4:6]
#pragma unroll
    for (int p = 0; p < 4; p++) {
        int row = p * 32 + mh * 16 + (m & 1) * 8 + rr;
        aoffx[p] = (uint32_t)(row * 128) | ((uint32_t)(row & 7) << 4);
    }
    uint32_t boffx[4];
#pragma unroll
    for (int t = 0; t < 4; t++) {
        int row = nq * 64 + t * 16 + (m >> 1) * 8 + rr;
        boffx[t] = (uint32_t)(16384 + row * 128) | ((uint32_t)(row & 7) << 4);
    }

    float acc[4][8][4];                 // [plane][n8-group][frag]
#pragma unroll
    for (int p = 0; p < 4; p++)
#pragma unroll
        for (int j = 0; j < 8; j++)
#pragma unroll
            for (int d = 0; d < 4; d++) acc[p][j][d] = 0.f;

    auto load_stage = [&](int c, int stage) {
        int br = c >> 4;
        uint32_t k = (uint32_t)(c & 15) * 128;          // 64 bf16 = 128B per chunk
        uint32_t st = smem + (uint32_t)stage * STAGE_BYTES;
        const char* A  = gA + (size_t)br * ((size_t)NM * B_ * K_ * 2) + k;
        const char* Bp = gB + (size_t)br * ((size_t)NG * K_ * 2) + k;
#pragma unroll
        for (int i = 0; i < 8; i++) {
            cp16(st + a_dst0 + i * 2048, A + a_srcs[i]);
            cp16(st + b_dst0 + i * 2048, Bp + b_src0 + (uint32_t)i * (16 * K_ * 2));
        }
    };

    auto compute_stage = [&](int stage) {
        uint32_t st = smem + (uint32_t)stage * STAGE_BYTES;
#pragma unroll
        for (int s = 0; s < 4; s++) {          // four k16 steps per BK=64
            uint32_t aks = (uint32_t)(s * 2 + akh) << 4;
            uint32_t bks = (uint32_t)(s * 2 + bkh) << 4;
            uint32_t a[4][4];
#pragma unroll
            for (int p = 0; p < 4; p++)
                ldsm4((st + aoffx[p]) ^ aks, a[p][0], a[p][1], a[p][2], a[p][3]);
#pragma unroll
            for (int t = 0; t < 4; t++) {
                uint32_t b[4];
                ldsm4((st + boffx[t]) ^ bks, b[0], b[1], b[2], b[3]);
#pragma unroll
                for (int p = 0; p < 4; p++) {
                    hmma(acc[p][2 * t],     a[p], &b[0]);
                    hmma(acc[p][2 * t + 1], a[p], &b[2]);
                }
            }
        }
    };

    // plane combine fully in-register -> direct global store/accumulate
    auto epilogue = [&](int br) {
        float av = br ? a11v : a1v;
        float sc0 = av * 0.0078125f;
#pragma unroll
        for (int j = 0; j < 8; j++) {
            int nnb = nq * 64 + j * 8 + (lane & 3) * 2;
#pragma unroll
            for (int d = 0; d < 4; d++) {
                int nn = nnb + (d & 1);
                int rw = mh * 16 + (lane >> 2) + (d >> 1) * 8;
                float bz = sbias[br][nn];
                float v = 0.f;
#pragma unroll
                for (int p = 0; p < 4; p++) {
                    float t = acc[p][j][d] * 0.0078125f + bz;
                    float q = fminf(fmaxf(rintf(t), -127.f), 127.f);
                    v += q * (sc0 / (float)(1 << p));
                }
                float* dst = &g_part[blk * 32 + rw][n0 + nn];
                if (br == 0) *dst = v; else *dst += v;
            }
        }
    };

    // ---- pipeline: 3 stages, 32 chunks (branch = chunk>>4) ----
#pragma unroll
    for (int c = 0; c < NSTAGES - 1; c++) {
        load_stage(c, c);
        asm volatile("cp.async.commit_group;" ::: "memory");
    }
    int ls = NSTAGES - 1;
    int cs = 0;
    for (int c = 0; c < TOTAL_CHUNKS; c++) {
        asm volatile("cp.async.wait_group %0;" :: "n"(NSTAGES - 2) : "memory");
        __syncthreads();
        if (c + NSTAGES - 1 < TOTAL_CHUNKS) load_stage(c + NSTAGES - 1, ls);
        asm volatile("cp.async.commit_group;" ::: "memory");
        if (++ls == NSTAGES) ls = 0;
        compute_stage(cs);
        if (++cs == NSTAGES) cs = 0;
        if (c == CHUNKS_PER_BRANCH - 1) {
            epilogue(0);
#pragma unroll
            for (int p = 0; p < 4; p++)
#pragma unroll
                for (int j = 0; j < 8; j++)
#pragma unroll
                    for (int d = 0; d < 4; d++) acc[p][j][d] = 0.f;
        }
    }
    epilogue(1);
}

// ======================= fused gate / cell elementwise =======================
__global__ void cell_kernel(const float* __restrict__ cx, float* __restrict__ out,
                            const float* a3, const float* a4, const float* a5,
                            const float* a6, const float* a7, const float* a8,
                            const float* a9, const float* a10, const float* a11) {
    int idx = blockIdx.x * blockDim.x + threadIdx.x;
    if (idx >= B_ * H_) return;
    int b = idx >> 10, h = idx & (H_ - 1);
    const float* row = &g_part[b][0];
    float gi = row[h];
    float gj = row[h + H_];
    float gf = row[h + 2 * H_];
    float go = row[h + 3 * H_];
    float v3 = *a3, v4 = *a4, v5 = *a5, v6 = *a6, v7 = *a7;
    float v8 = *a8, v9 = *a9, v10 = *a10, v11 = *a11;

    float fg  = qr8(pact_f(sigmoidf_fast(gf), v3), v3);
    float ig  = qr8(pact_f(sigmoidf_fast(gi), v4), v4);
    float act = qr8(pact_f(tanhf_fast(gj),    v5), v5);
    float og  = qr8(pact_f(sigmoidf_fast(go), v6), v6);
    float gc  = qr8(pact_f(cx[idx] * fg,  v7), v7);
    float ai  = qr8(pact_f(ig * act,      v8), v8);
    float nc  = qr8(pact_f(gc + ai,       v9), v9);
    float ac  = qr8(pact_f(tanhf_fast(nc), v10), v10);
    float nh  = qr8(pact_f(ac * og,       v11), v11);

    out[idx]           = nh;
    out[B_ * H_ + idx] = nc;
}

// ======================= launch =======================
extern "C" void kernel_launch(void* const* d_in, const int* in_sizes, int n_in,
                              void* d_out, int out_size) {
    const float* input = (const float*)d_in[0];
    const float* hx    = (const float*)d_in[1];
    const float* cx    = (const float*)d_in[2];
    const float* wih   = (const float*)d_in[3];
    const float* whh   = (const float*)d_in[4];
    const float* bih   = (const float*)d_in[5];
    const float* bhh   = (const float*)d_in[6];
    const float* a1    = (const float*)d_in[7];
    const float* a3    = (const float*)d_in[8];
    const float* a4    = (const float*)d_in[9];
    const float* a5    = (const float*)d_in[10];
    const float* a6    = (const float*)d_in[11];
    const float* a7    = (const float*)d_in[12];
    const float* a8    = (const float*)d_in[13];
    const float* a9    = (const float*)d_in[14];
    const float* a10   = (const float*)d_in[15];
    const float* a11   = (const float*)d_in[16];
    float* out = (float*)d_out;

    static int configured = 0;
    if (!configured) {
        cudaFuncSetAttribute(gemm_bf16, cudaFuncAttributeMaxDynamicSharedMemorySize,
                             DSM_BYTES);
        configured = 1;
    }

    prep_kernel<<<16384, 256>>>(input, hx, wih, whh, a1, a11);

    gemm_bf16<<<4096, 128, DSM_BYTES>>>(a1, a11, bih, bhh);

    cell_kernel<<<(B_ * H_ + 255) / 256, 256>>>(cx, out, a3, a4, a5, a6, a7,
                                                a8, a9, a10, a11);
}